// round 12
// baseline (speedup 1.0000x reference)
#include <cuda_runtime.h>
#include <cuda_bf16.h>
#include <cstdint>

#define N_ROWS   65536
#define K_CENT   512
#define D_DIM    1024
#define TILE_M   128
#define CH_N     256          // centers per chunk
#define NCHUNK   2
#define KSLAB    64
#define NSLABS   (D_DIM / KSLAB)   // 16
#define TAU_F    0.1f
#define EPS_F    1e-8f

// Normalized centers in bf16 (1/||c|| folded in), row-major [K_CENT][D_DIM]
__device__ __align__(16) __nv_bfloat16 g_cbf[K_CENT * D_DIM];
// Normalized embeddings in bf16 with 1/(||e||*tau) folded in, [N_ROWS][D_DIM]
__device__ __align__(16) __nv_bfloat16 g_ebf[(size_t)N_ROWS * D_DIM];
// Per-chunk partial softmax stats
__device__ float g_pm[NCHUNK * N_ROWS];
__device__ float g_ps[NCHUNK * N_ROWS];
__device__ float g_plv[NCHUNK * N_ROWS];
// Per-mtile completion counters (self-resetting each replay)
__device__ int g_cnt[N_ROWS / TILE_M];

// ---------------- helpers ----------------
__device__ __forceinline__ uint32_t smem_u32(const void* p) {
    uint32_t a;
    asm("{ .reg .u64 t; cvta.to.shared.u64 t, %1; cvt.u32.u64 %0, t; }" : "=r"(a) : "l"(p));
    return a;
}
#define SWZ(o) ((o) ^ ((((uint32_t)(o)) >> 3) & 0x70u))

__device__ __forceinline__ void cp16(uint32_t dst, const void* src) {
    asm volatile("cp.async.cg.shared.global [%0], [%1], 16;"
                 :: "r"(dst), "l"(__cvta_generic_to_global(src)) : "memory");
}
#define CP_COMMIT() asm volatile("cp.async.commit_group;" ::: "memory")
#define CP_WAIT2()  asm volatile("cp.async.wait_group 2;" ::: "memory")

__device__ __forceinline__ void ldsm4(uint32_t* r, uint32_t addr) {
    asm volatile("ldmatrix.sync.aligned.m8n8.x4.shared.b16 {%0,%1,%2,%3}, [%4];"
                 : "=r"(r[0]), "=r"(r[1]), "=r"(r[2]), "=r"(r[3]) : "r"(addr));
}

__device__ __forceinline__ void mma16816(float* d, const uint32_t* a,
                                         uint32_t b0, uint32_t b1) {
    asm volatile(
        "mma.sync.aligned.m16n8k16.row.col.f32.bf16.bf16.f32 "
        "{%0,%1,%2,%3}, {%4,%5,%6,%7}, {%8,%9}, {%0,%1,%2,%3};"
        : "+f"(d[0]), "+f"(d[1]), "+f"(d[2]), "+f"(d[3])
        : "r"(a[0]), "r"(a[1]), "r"(a[2]), "r"(a[3]), "r"(b0), "r"(b1));
}

__device__ __forceinline__ uint32_t pk(float x, float y) {
    __nv_bfloat162 h = __floats2bfloat162_rn(x, y);
    return *reinterpret_cast<uint32_t*>(&h);
}

// ---------------- Kernel 1: merged prep (centers + embeddings) ----------------
#define PREP_CENTER_BLOCKS 512
__global__ void __launch_bounds__(256) prep_kernel(const float* __restrict__ centers,
                                                   const float* __restrict__ emb,
                                                   float* __restrict__ out) {
    const int bid = blockIdx.x;
    const int t = threadIdx.x;

    if (bid < PREP_CENTER_BLOCKS) {
        __shared__ float wss[8];
        const int row = bid;
        float4 v = reinterpret_cast<const float4*>(centers + (size_t)row * D_DIM)[t];
        float ss = v.x * v.x + v.y * v.y + v.z * v.z + v.w * v.w;
#pragma unroll
        for (int o = 16; o; o >>= 1) ss += __shfl_xor_sync(0xFFFFFFFFu, ss, o);
        if ((t & 31) == 0) wss[t >> 5] = ss;
        __syncthreads();
        if (t < 32) {
            float x = (t < 8) ? wss[t] : 0.f;
#pragma unroll
            for (int o = 4; o; o >>= 1) x += __shfl_xor_sync(0xFFFFFFFFu, x, o);
            if (t == 0) wss[0] = x;
        }
        __syncthreads();
        const float sc = 1.0f / fmaxf(sqrtf(wss[0]), EPS_F);

        __nv_bfloat162* orow = reinterpret_cast<__nv_bfloat162*>(g_cbf + (size_t)row * D_DIM);
        orow[t * 2]     = __floats2bfloat162_rn(v.x * sc, v.y * sc);
        orow[t * 2 + 1] = __floats2bfloat162_rn(v.z * sc, v.w * sc);

        if (row == 0 && t == 0) out[0] = 0.f;
        return;
    }

    // embeddings path
    const int lane = t & 31;
    const int wrp  = t >> 5;
    const int row  = (bid - PREP_CENTER_BLOCKS) * 8 + wrp;

    const float4* src = reinterpret_cast<const float4*>(emb + (size_t)row * D_DIM);
    float4 v[8];
    float ss = 0.f;
#pragma unroll
    for (int j = 0; j < 8; ++j) {
        v[j] = src[lane + j * 32];
        ss += v[j].x * v[j].x + v[j].y * v[j].y + v[j].z * v[j].z + v[j].w * v[j].w;
    }
#pragma unroll
    for (int o = 16; o; o >>= 1) ss += __shfl_xor_sync(0xFFFFFFFFu, ss, o);
    const float sc = 1.0f / (fmaxf(sqrtf(ss), EPS_F) * TAU_F);

    uint2* dst = reinterpret_cast<uint2*>(g_ebf + (size_t)row * D_DIM);
#pragma unroll
    for (int j = 0; j < 8; ++j) {
        uint2 o;
        o.x = pk(v[j].x * sc, v[j].y * sc);
        o.y = pk(v[j].z * sc, v[j].w * sc);
        dst[lane + j * 32] = o;
    }
}

// ---------------- Kernel 2: GEMM chunk, 512 thr, 4-stage, de-convoyed ----------------
// grid = 1024: mtile = bid>>1 (128 rows), chunk = bid&1 (256 centers)
// 16 warps 4(m)x4(n): warp tile 32 rows x 64 cols, acc 64 f32 regs
#define A_STG     16384u
#define B_STG     32768u
#define OFF_A     0u              // 4 x 16384 = 65536
#define OFF_B     65536u          // 4 x 32768 = 131072 -> end 196608
#define OFF_MM    196608u         // 512 f
#define OFF_MS    198656u
#define OFF_MLV   200704u         // end 202752
#define SMEM_DYN  (202752 + 1024)

__global__ void __launch_bounds__(512, 1)
gemm_chunk_kernel(const long long* __restrict__ labels,
                  float* __restrict__ out) {
    extern __shared__ uint8_t dyn[];
    const uint32_t sb = smem_u32(dyn);
    const uint32_t base = (sb + 1023u) & ~1023u;
    uint8_t* gbase = dyn + (base - sb);

    float* sm_m  = reinterpret_cast<float*>(gbase + OFF_MM);
    float* sm_s  = reinterpret_cast<float*>(gbase + OFF_MS);
    float* sm_lv = reinterpret_cast<float*>(gbase + OFF_MLV);

    const int t     = threadIdx.x;
    const int lane  = t & 31;
    const int wid   = t >> 5;
    const int wm    = wid & 3;    // 32-row slice
    const int wn    = wid >> 2;   // 64-col slice
    const int bid   = blockIdx.x;
    const int mtile = bid >> 1;
    const int chunk = bid & 1;
    const int row0  = mtile * TILE_M;

    // loader mappings (16B chunks): c -> row = c>>3, off8 = c&7
    const int ar = t >> 3, ao = t & 7;
    const uint32_t a_sw0 = SWZ((uint32_t)(ar * 128 + ao * 16));
    const uint32_t a_sw1 = SWZ((uint32_t)((ar + 64) * 128 + ao * 16));
    const __nv_bfloat16* agp = g_ebf + (size_t)(row0 + ar) * D_DIM + ao * 8;
    const __nv_bfloat16* bgp = g_cbf + (size_t)(chunk * CH_N + ar) * D_DIM + ao * 8;

    // one quarter of a slab's loads (A: parts 0-1; B: parts 2-3 carry 2 rows each)
    auto issue_part = [&](int kb, int stg, int part) {
        if (part == 0) {
            cp16(base + OFF_A + (uint32_t)stg * A_STG + a_sw0, agp + kb * KSLAB);
        } else if (part == 1) {
            cp16(base + OFF_A + (uint32_t)stg * A_STG + a_sw1,
                 agp + kb * KSLAB + (size_t)64 * D_DIM);
        } else {
            const uint32_t Bd = base + OFF_B + (uint32_t)stg * B_STG;
            const __nv_bfloat16* s = bgp + kb * KSLAB;
            const int i0 = (part - 2) * 2;
#pragma unroll
            for (int i = i0; i < i0 + 2; ++i)
                cp16(Bd + SWZ((uint32_t)((ar + i * 64) * 128 + ao * 16)),
                     s + (size_t)(i * 64) * D_DIM);
        }
    };
    auto issue_all = [&](int kb, int stg) {
#pragma unroll
        for (int p = 0; p < 4; ++p) issue_part(kb, stg, p);
    };

    float acc[2][8][4];
#pragma unroll
    for (int am = 0; am < 2; ++am)
#pragma unroll
        for (int an = 0; an < 8; ++an)
#pragma unroll
            for (int k = 0; k < 4; ++k) acc[am][an][k] = 0.f;

    // ---- prologue: stages 0..2 in flight ----
    issue_all(0, 0); CP_COMMIT();
    issue_all(1, 1); CP_COMMIT();
    issue_all(2, 2); CP_COMMIT();

    const int rlow = lane & 15;
    const int bhi  = (lane >> 4) * 16;
    const int krot = wid & 3;     // per-warp k-step rotation (de-convoy)

#pragma unroll 1
    for (int kb = 0; kb < NSLABS; ++kb) {
        const int stg = kb & 3;
        const uint32_t Ab = base + OFF_A + (uint32_t)stg * A_STG;
        const uint32_t Bb = base + OFF_B + (uint32_t)stg * B_STG;
        const int nstg = (kb + 3) & 3;
        const bool do_issue = (kb + 3 < NSLABS);

        CP_WAIT2();              // slab kb resident (2 newer groups pending)
        __syncthreads();         // all warps past slab kb-1 -> stage reuse safe

#pragma unroll
        for (int ksi = 0; ksi < 4; ++ksi) {
            const int ks = (ksi + krot) & 3;   // rotated k-step order
            if (do_issue) issue_part(kb + 3, nstg, ksi);  // spread DMA issue

            const uint32_t byt = (uint32_t)(ks * 32 + bhi);
            uint32_t af[2][4], bf[4][4];
#pragma unroll
            for (int am = 0; am < 2; ++am)
                ldsm4(af[am], Ab + SWZ((uint32_t)((wm * 32 + am * 16 + rlow) * 128) + byt));
#pragma unroll
            for (int p = 0; p < 4; ++p)
                ldsm4(bf[p], Bb + SWZ((uint32_t)((wn * 64 + p * 16 + rlow) * 128) + byt));
#pragma unroll
            for (int am = 0; am < 2; ++am)
#pragma unroll
                for (int p = 0; p < 4; ++p) {
                    mma16816(acc[am][2 * p],     af[am], bf[p][0], bf[p][2]);
                    mma16816(acc[am][2 * p + 1], af[am], bf[p][1], bf[p][3]);
                }
        }
        CP_COMMIT();             // one group per slab keeps wait_group 2 aligned
    }
    __syncthreads();

    // ---- per-warp partial softmax over its 64 cols (scale pre-folded) ----
    const int ql = lane >> 2, qc = lane & 3;
#pragma unroll
    for (int am = 0; am < 2; ++am) {
#pragma unroll
        for (int h = 0; h < 2; ++h) {
            const int r = wm * 32 + am * 16 + ql + 8 * h;
            const int lc = (int)labels[row0 + r];

            float m = -1e30f;
            float v[16];
#pragma unroll
            for (int an = 0; an < 8; ++an)
#pragma unroll
                for (int e = 0; e < 2; ++e) {
                    float x = acc[am][an][2 * h + e];
                    v[an * 2 + e] = x;
                    m = fmaxf(m, x);
                }
            m = fmaxf(m, __shfl_xor_sync(0xFFFFFFFFu, m, 1));
            m = fmaxf(m, __shfl_xor_sync(0xFFFFFFFFu, m, 2));

            float s = 0.f, lv = 0.f;
#pragma unroll
            for (int an = 0; an < 8; ++an)
#pragma unroll
                for (int e = 0; e < 2; ++e) {
                    s += __expf(v[an * 2 + e] - m);
                    const int col = chunk * CH_N + wn * 64 + an * 8 + qc * 2 + e;
                    if (col == lc) lv = v[an * 2 + e];
                }
            s  += __shfl_xor_sync(0xFFFFFFFFu, s, 1);
            s  += __shfl_xor_sync(0xFFFFFFFFu, s, 2);
            lv += __shfl_xor_sync(0xFFFFFFFFu, lv, 1);
            lv += __shfl_xor_sync(0xFFFFFFFFu, lv, 2);

            if (qc == 0) {
                sm_m[wn * 128 + r]  = m;
                sm_s[wn * 128 + r]  = s;
                sm_lv[wn * 128 + r] = lv;
            }
        }
    }
    __syncthreads();

    // ---- merge 4 warp-columns, write chunk partials ----
    if (t < TILE_M) {
        float M = -1e30f;
#pragma unroll
        for (int w = 0; w < 4; ++w) M = fmaxf(M, sm_m[w * 128 + t]);
        float S = 0.f, LV = 0.f;
#pragma unroll
        for (int w = 0; w < 4; ++w) {
            S  += sm_s[w * 128 + t] * __expf(sm_m[w * 128 + t] - M);
            LV += sm_lv[w * 128 + t];
        }
        const int gr = row0 + t;
        g_pm[chunk * N_ROWS + gr]  = M;
        g_ps[chunk * N_ROWS + gr]  = S;
        g_plv[chunk * N_ROWS + gr] = LV;
        __threadfence();          // publish partials before counter bump
    }
    __syncthreads();

    // ---- fused finalize: last chunk-CTA of this mtile merges & accumulates ----
    __shared__ int s_last;
    if (t == 0) {
        int old = atomicAdd(&g_cnt[mtile], 1);
        s_last = (old == NCHUNK - 1) ? 1 : 0;
    }
    __syncthreads();
    if (s_last) {
        __threadfence();          // acquire: other chunk's partials visible
        float loss = 0.f;
        if (t < TILE_M) {
            const int gr = row0 + t;
            float M = -1e30f;
#pragma unroll
            for (int c = 0; c < NCHUNK; ++c) M = fmaxf(M, g_pm[c * N_ROWS + gr]);
            float S = 0.f, LV = 0.f;
#pragma unroll
            for (int c = 0; c < NCHUNK; ++c) {
                S  += g_ps[c * N_ROWS + gr] * __expf(g_pm[c * N_ROWS + gr] - M);
                LV += g_plv[c * N_ROWS + gr];
            }
            loss = (M + logf(S)) - LV;
        }
#pragma unroll
        for (int o = 16; o; o >>= 1) loss += __shfl_xor_sync(0xFFFFFFFFu, loss, o);
        __shared__ float wsum[16];
        if ((t & 31) == 0) wsum[t >> 5] = loss;
        __syncthreads();
        if (t < 32) {
            float x = (t < 16) ? wsum[t] : 0.f;
#pragma unroll
            for (int o = 8; o; o >>= 1) x += __shfl_xor_sync(0xFFFFFFFFu, x, o);
            if (t == 0) {
                atomicAdd(out, x * (1.0f / (float)N_ROWS));
                g_cnt[mtile] = 0;   // self-reset for next graph replay
            }
        }
    }
}

// ---------------- Launch ----------------
extern "C" void kernel_launch(void* const* d_in, const int* in_sizes, int n_in,
                              void* d_out, int out_size) {
    const float* emb       = (const float*)d_in[0];
    const float* centers   = (const float*)d_in[1];
    const long long* label = (const long long*)d_in[2];
    float* out             = (float*)d_out;

    cudaFuncSetAttribute(gemm_chunk_kernel, cudaFuncAttributeMaxDynamicSharedMemorySize, SMEM_DYN);

    prep_kernel<<<PREP_CENTER_BLOCKS + N_ROWS / 8, 256>>>(centers, emb, out);
    gemm_chunk_kernel<<<(N_ROWS / TILE_M) * NCHUNK, 512, SMEM_DYN>>>(label, out);
}

// round 13
// speedup vs baseline: 1.0165x; 1.0165x over previous
#include <cuda_runtime.h>
#include <cuda_bf16.h>
#include <cstdint>

#define N_ROWS   65536
#define K_CENT   512
#define D_DIM    1024
#define TILE_M   128
#define CH_N     128          // centers per chunk
#define NCHUNK   4
#define KSLAB    64
#define NSLABS   (D_DIM / KSLAB)   // 16
#define TAU_F    0.1f
#define EPS_F    1e-8f

// Normalized centers in bf16 (1/||c|| folded in), row-major [K_CENT][D_DIM]
__device__ __align__(16) __nv_bfloat16 g_cbf[K_CENT * D_DIM];
// Normalized embeddings in bf16 with 1/(||e||*tau) folded in, [N_ROWS][D_DIM]
__device__ __align__(16) __nv_bfloat16 g_ebf[(size_t)N_ROWS * D_DIM];
// Per-chunk partial softmax stats
__device__ float g_pm[NCHUNK * N_ROWS];
__device__ float g_ps[NCHUNK * N_ROWS];
__device__ float g_plv[NCHUNK * N_ROWS];
// Per-mtile completion counters (self-resetting each replay)
__device__ int g_cnt[N_ROWS / TILE_M];

// ---------------- helpers ----------------
__device__ __forceinline__ uint32_t smem_u32(const void* p) {
    uint32_t a;
    asm("{ .reg .u64 t; cvta.to.shared.u64 t, %1; cvt.u32.u64 %0, t; }" : "=r"(a) : "l"(p));
    return a;
}
#define SWZ(o) ((o) ^ ((((uint32_t)(o)) >> 3) & 0x70u))

__device__ __forceinline__ void cp16(uint32_t dst, const void* src) {
    asm volatile("cp.async.cg.shared.global [%0], [%1], 16;"
                 :: "r"(dst), "l"(__cvta_generic_to_global(src)) : "memory");
}
#define CP_COMMIT() asm volatile("cp.async.commit_group;" ::: "memory")
#define CP_WAIT1()  asm volatile("cp.async.wait_group 1;" ::: "memory")

__device__ __forceinline__ void ldsm4(uint32_t* r, uint32_t addr) {
    asm volatile("ldmatrix.sync.aligned.m8n8.x4.shared.b16 {%0,%1,%2,%3}, [%4];"
                 : "=r"(r[0]), "=r"(r[1]), "=r"(r[2]), "=r"(r[3]) : "r"(addr));
}

__device__ __forceinline__ void mma16816(float* d, const uint32_t* a,
                                         uint32_t b0, uint32_t b1) {
    asm volatile(
        "mma.sync.aligned.m16n8k16.row.col.f32.bf16.bf16.f32 "
        "{%0,%1,%2,%3}, {%4,%5,%6,%7}, {%8,%9}, {%0,%1,%2,%3};"
        : "+f"(d[0]), "+f"(d[1]), "+f"(d[2]), "+f"(d[3])
        : "r"(a[0]), "r"(a[1]), "r"(a[2]), "r"(a[3]), "r"(b0), "r"(b1));
}

__device__ __forceinline__ uint32_t pk(float x, float y) {
    __nv_bfloat162 h = __floats2bfloat162_rn(x, y);
    return *reinterpret_cast<uint32_t*>(&h);
}

// ---------------- Kernel 1: merged prep (centers + embeddings) ----------------
#define PREP_CENTER_BLOCKS 512
__global__ void __launch_bounds__(256) prep_kernel(const float* __restrict__ centers,
                                                   const float* __restrict__ emb,
                                                   float* __restrict__ out) {
    const int bid = blockIdx.x;
    const int t = threadIdx.x;

    if (bid < PREP_CENTER_BLOCKS) {
        __shared__ float wss[8];
        const int row = bid;
        float4 v = reinterpret_cast<const float4*>(centers + (size_t)row * D_DIM)[t];
        float ss = v.x * v.x + v.y * v.y + v.z * v.z + v.w * v.w;
#pragma unroll
        for (int o = 16; o; o >>= 1) ss += __shfl_xor_sync(0xFFFFFFFFu, ss, o);
        if ((t & 31) == 0) wss[t >> 5] = ss;
        __syncthreads();
        if (t < 32) {
            float x = (t < 8) ? wss[t] : 0.f;
#pragma unroll
            for (int o = 4; o; o >>= 1) x += __shfl_xor_sync(0xFFFFFFFFu, x, o);
            if (t == 0) wss[0] = x;
        }
        __syncthreads();
        const float sc = 1.0f / fmaxf(sqrtf(wss[0]), EPS_F);

        __nv_bfloat162* orow = reinterpret_cast<__nv_bfloat162*>(g_cbf + (size_t)row * D_DIM);
        orow[t * 2]     = __floats2bfloat162_rn(v.x * sc, v.y * sc);
        orow[t * 2 + 1] = __floats2bfloat162_rn(v.z * sc, v.w * sc);

        if (row == 0 && t == 0) out[0] = 0.f;
        return;
    }

    // embeddings path
    const int lane = t & 31;
    const int wrp  = t >> 5;
    const int row  = (bid - PREP_CENTER_BLOCKS) * 8 + wrp;

    const float4* src = reinterpret_cast<const float4*>(emb + (size_t)row * D_DIM);
    float4 v[8];
    float ss = 0.f;
#pragma unroll
    for (int j = 0; j < 8; ++j) {
        v[j] = src[lane + j * 32];
        ss += v[j].x * v[j].x + v[j].y * v[j].y + v[j].z * v[j].z + v[j].w * v[j].w;
    }
#pragma unroll
    for (int o = 16; o; o >>= 1) ss += __shfl_xor_sync(0xFFFFFFFFu, ss, o);
    const float sc = 1.0f / (fmaxf(sqrtf(ss), EPS_F) * TAU_F);

    uint2* dst = reinterpret_cast<uint2*>(g_ebf + (size_t)row * D_DIM);
#pragma unroll
    for (int j = 0; j < 8; ++j) {
        uint2 o;
        o.x = pk(v[j].x * sc, v[j].y * sc);
        o.y = pk(v[j].z * sc, v[j].w * sc);
        dst[lane + j * 32] = o;
    }
}

// ---------------- Kernel 2: GEMM chunk, 256 thr, 2 CTAs/SM, fused finalize ----------
// grid = 2048: mtile = bid>>2 (128 rows), chunk = bid&3 (128 centers)
// 8 warps, 2(m) x 4(n): warp tile 64 rows x 32 cols, acc 64 regs
#define A_STG     16384u
#define B_STG     16384u
#define OFF_A     0u
#define OFF_B     49152u
#define OFF_MM    98304u          // 512 f
#define OFF_MS    100352u
#define OFF_MLV   102400u         // end 104448
#define SMEM_DYN  (104448 + 1024)

__global__ void __launch_bounds__(256, 2)
gemm_chunk_kernel(const long long* __restrict__ labels,
                  float* __restrict__ out) {
    extern __shared__ uint8_t dyn[];
    const uint32_t sb = smem_u32(dyn);
    const uint32_t base = (sb + 1023u) & ~1023u;
    uint8_t* gbase = dyn + (base - sb);

    float* sm_m  = reinterpret_cast<float*>(gbase + OFF_MM);
    float* sm_s  = reinterpret_cast<float*>(gbase + OFF_MS);
    float* sm_lv = reinterpret_cast<float*>(gbase + OFF_MLV);

    const int t     = threadIdx.x;
    const int lane  = t & 31;
    const int wid   = t >> 5;
    const int wm    = wid & 1;    // 64-row slice
    const int wn    = wid >> 1;   // 32-col slice
    const int bid   = blockIdx.x;
    const int mtile = bid >> 2;
    const int chunk = bid & 3;
    const int row0  = mtile * TILE_M;

    // loader mapping: 16B chunk c = t + i*256 -> row = (t>>3) + i*32, off8 = t&7
    const int lr = t >> 3, lo = t & 7;
    uint32_t l_sw[4];
#pragma unroll
    for (int i = 0; i < 4; ++i)
        l_sw[i] = SWZ((uint32_t)((lr + i * 32) * 128 + lo * 16));
    const __nv_bfloat16* agp = g_ebf + (size_t)(row0 + lr) * D_DIM + lo * 8;
    const __nv_bfloat16* bgp = g_cbf + (size_t)(chunk * CH_N + lr) * D_DIM + lo * 8;

    // issue one quarter (A chunk i + B chunk i) of slab kb into stage stg
    auto issue_part = [&](int kb, int stg, int i) {
        const uint32_t Ad = base + OFF_A + (uint32_t)stg * A_STG;
        const uint32_t Bd = base + OFF_B + (uint32_t)stg * B_STG;
        cp16(Ad + l_sw[i], agp + kb * KSLAB + (size_t)(i * 32) * D_DIM);
        cp16(Bd + l_sw[i], bgp + kb * KSLAB + (size_t)(i * 32) * D_DIM);
    };

    float acc[4][4][4];
#pragma unroll
    for (int am = 0; am < 4; ++am)
#pragma unroll
        for (int an = 0; an < 4; ++an)
#pragma unroll
            for (int k = 0; k < 4; ++k) acc[am][an][k] = 0.f;

    // ---- prologue: stages 0,1 in flight ----
#pragma unroll
    for (int i = 0; i < 4; ++i) issue_part(0, 0, i);
    CP_COMMIT();
#pragma unroll
    for (int i = 0; i < 4; ++i) issue_part(1, 1, i);
    CP_COMMIT();

    const int rlow = lane & 15;
    const int bhi  = (lane >> 4) * 16;
    // per-warp k-step rotation; CTA-parity offset decorrelates co-resident CTAs
    const int krot = (wid + ((bid & 1) << 1)) & 3;

#pragma unroll 1
    for (int kb = 0; kb < NSLABS; ++kb) {
        const int stg = kb % 3;
        const uint32_t Ab = base + OFF_A + (uint32_t)stg * A_STG;
        const uint32_t Bb = base + OFF_B + (uint32_t)stg * B_STG;
        const int nstg = (kb + 2) % 3;
        const bool do_issue = (kb + 2 < NSLABS);

        CP_WAIT1();              // slab kb resident (kb+1 may be pending)
        __syncthreads();         // all warps done with slab kb-1 -> stage (kb+2)%3 free

        // B-fragment double buffer: preload ks0 of (rotated) sequence
        uint32_t bfb[2][2][4];
        {
            const int ks0 = krot;
            const uint32_t byt0 = (uint32_t)(ks0 * 32 + bhi);
#pragma unroll
            for (int p = 0; p < 2; ++p)
                ldsm4(bfb[0][p], Bb + SWZ((uint32_t)((wn * 32 + p * 16 + rlow) * 128) + byt0));
        }

#pragma unroll
        for (int ksi = 0; ksi < 4; ++ksi) {
            const int ks = (ksi + krot) & 3;   // rotated k-step order
            const int cur = ksi & 1;
            const uint32_t byt = (uint32_t)(ks * 32 + bhi);

            // A fragments for this step
            uint32_t af[4][4];
#pragma unroll
            for (int am = 0; am < 4; ++am)
                ldsm4(af[am], Ab + SWZ((uint32_t)((wm * 64 + am * 16 + rlow) * 128) + byt));

            // prefetch B fragments for next step (fills ldsm->MMA shadow)
            if (ksi < 3) {
                const int ksn = (ksi + 1 + krot) & 3;
                const uint32_t bytn = (uint32_t)(ksn * 32 + bhi);
#pragma unroll
                for (int p = 0; p < 2; ++p)
                    ldsm4(bfb[cur ^ 1][p],
                          Bb + SWZ((uint32_t)((wn * 32 + p * 16 + rlow) * 128) + bytn));
            }

            // spread next-slab cp.async issue into the ldsm shadow
            if (do_issue) issue_part(kb + 2, nstg, ksi);

#pragma unroll
            for (int am = 0; am < 4; ++am)
#pragma unroll
                for (int p = 0; p < 2; ++p) {
                    mma16816(acc[am][2 * p],     af[am], bfb[cur][p][0], bfb[cur][p][2]);
                    mma16816(acc[am][2 * p + 1], af[am], bfb[cur][p][1], bfb[cur][p][3]);
                }
        }
        CP_COMMIT();             // one group per slab keeps wait_group 1 aligned
    }
    __syncthreads();

    // ---- per-warp partial softmax over its 32 cols (scale pre-folded) ----
    const int ql = lane >> 2, qc = lane & 3;
#pragma unroll
    for (int am = 0; am < 4; ++am) {
#pragma unroll
        for (int h = 0; h < 2; ++h) {
            const int r = wm * 64 + am * 16 + ql + 8 * h;
            const int lc = (int)labels[row0 + r];

            float m = -1e30f;
            float v[8];
#pragma unroll
            for (int an = 0; an < 4; ++an)
#pragma unroll
                for (int e = 0; e < 2; ++e) {
                    float x = acc[am][an][2 * h + e];
                    v[an * 2 + e] = x;
                    m = fmaxf(m, x);
                }
            m = fmaxf(m, __shfl_xor_sync(0xFFFFFFFFu, m, 1));
            m = fmaxf(m, __shfl_xor_sync(0xFFFFFFFFu, m, 2));

            float s = 0.f, lv = 0.f;
#pragma unroll
            for (int an = 0; an < 4; ++an)
#pragma unroll
                for (int e = 0; e < 2; ++e) {
                    s += __expf(v[an * 2 + e] - m);
                    const int col = chunk * CH_N + wn * 32 + an * 8 + qc * 2 + e;
                    if (col == lc) lv = v[an * 2 + e];
                }
            s  += __shfl_xor_sync(0xFFFFFFFFu, s, 1);
            s  += __shfl_xor_sync(0xFFFFFFFFu, s, 2);
            lv += __shfl_xor_sync(0xFFFFFFFFu, lv, 1);
            lv += __shfl_xor_sync(0xFFFFFFFFu, lv, 2);

            if (qc == 0) {
                sm_m[wn * 128 + r]  = m;
                sm_s[wn * 128 + r]  = s;
                sm_lv[wn * 128 + r] = lv;
            }
        }
    }
    __syncthreads();

    // ---- merge 4 warp-columns, write chunk partials ----
    if (t < TILE_M) {
        float M = -1e30f;
#pragma unroll
        for (int w = 0; w < 4; ++w) M = fmaxf(M, sm_m[w * 128 + t]);
        float S = 0.f, LV = 0.f;
#pragma unroll
        for (int w = 0; w < 4; ++w) {
            S  += sm_s[w * 128 + t] * __expf(sm_m[w * 128 + t] - M);
            LV += sm_lv[w * 128 + t];
        }
        const int gr = row0 + t;
        g_pm[chunk * N_ROWS + gr]  = M;
        g_ps[chunk * N_ROWS + gr]  = S;
        g_plv[chunk * N_ROWS + gr] = LV;
        __threadfence();          // publish partials before counter bump
    }
    __syncthreads();

    // ---- fused finalize: last chunk-CTA of this mtile merges & accumulates ----
    __shared__ int s_last;
    if (t == 0) {
        int old = atomicAdd(&g_cnt[mtile], 1);
        s_last = (old == NCHUNK - 1) ? 1 : 0;
    }
    __syncthreads();
    if (s_last) {
        __threadfence();          // acquire: other chunks' partials visible
        float loss = 0.f;
        if (t < TILE_M) {
            const int gr = row0 + t;
            float M = -1e30f;
#pragma unroll
            for (int c = 0; c < NCHUNK; ++c) M = fmaxf(M, g_pm[c * N_ROWS + gr]);
            float S = 0.f, LV = 0.f;
#pragma unroll
            for (int c = 0; c < NCHUNK; ++c) {
                S  += g_ps[c * N_ROWS + gr] * __expf(g_pm[c * N_ROWS + gr] - M);
                LV += g_plv[c * N_ROWS + gr];
            }
            loss = (M + logf(S)) - LV;
        }
#pragma unroll
        for (int o = 16; o; o >>= 1) loss += __shfl_xor_sync(0xFFFFFFFFu, loss, o);
        __shared__ float wsum[8];
        if ((t & 31) == 0) wsum[t >> 5] = loss;
        __syncthreads();
        if (t < 32) {
            float x = (t < 8) ? wsum[t] : 0.f;
#pragma unroll
            for (int o = 4; o; o >>= 1) x += __shfl_xor_sync(0xFFFFFFFFu, x, o);
            if (t == 0) {
                atomicAdd(out, x * (1.0f / (float)N_ROWS));
                g_cnt[mtile] = 0;   // self-reset for next graph replay
            }
        }
    }
}

// ---------------- Launch ----------------
extern "C" void kernel_launch(void* const* d_in, const int* in_sizes, int n_in,
                              void* d_out, int out_size) {
    const float* emb       = (const float*)d_in[0];
    const float* centers   = (const float*)d_in[1];
    const long long* label = (const long long*)d_in[2];
    float* out             = (float*)d_out;

    cudaFuncSetAttribute(gemm_chunk_kernel, cudaFuncAttributeMaxDynamicSharedMemorySize, SMEM_DYN);

    prep_kernel<<<PREP_CENTER_BLOCKS + N_ROWS / 8, 256>>>(centers, emb, out);
    gemm_chunk_kernel<<<(N_ROWS / TILE_M) * NCHUNK, 256, SMEM_DYN>>>(label, out);
}

// round 14
// speedup vs baseline: 1.0489x; 1.0318x over previous
#include <cuda_runtime.h>
#include <cuda_bf16.h>
#include <cstdint>

#define N_ROWS   65536
#define K_CENT   512
#define D_DIM    1024
#define TILE_M   128
#define CH_N     128          // centers per chunk
#define NCHUNK   4
#define KSLAB    64
#define NSLABS   (D_DIM / KSLAB)   // 16
#define TAU_F    0.1f
#define EPS_F    1e-8f

// Normalized centers in bf16 (1/||c|| folded in), row-major [K_CENT][D_DIM]
__device__ __align__(16) __nv_bfloat16 g_cbf[K_CENT * D_DIM];
// Normalized embeddings in bf16 with 1/(||e||*tau) folded in, [N_ROWS][D_DIM]
__device__ __align__(16) __nv_bfloat16 g_ebf[(size_t)N_ROWS * D_DIM];
// Per-chunk partial softmax stats
__device__ float g_pm[NCHUNK * N_ROWS];
__device__ float g_ps[NCHUNK * N_ROWS];
__device__ float g_plv[NCHUNK * N_ROWS];
// Per-mtile completion counters (self-resetting each replay)
__device__ int g_cnt[N_ROWS / TILE_M];

// ---------------- helpers ----------------
__device__ __forceinline__ uint32_t smem_u32(const void* p) {
    uint32_t a;
    asm("{ .reg .u64 t; cvta.to.shared.u64 t, %1; cvt.u32.u64 %0, t; }" : "=r"(a) : "l"(p));
    return a;
}
#define SWZ(o) ((o) ^ ((((uint32_t)(o)) >> 3) & 0x70u))

__device__ __forceinline__ void cp16(uint32_t dst, const void* src) {
    asm volatile("cp.async.cg.shared.global [%0], [%1], 16;"
                 :: "r"(dst), "l"(__cvta_generic_to_global(src)) : "memory");
}
#define CP_COMMIT() asm volatile("cp.async.commit_group;" ::: "memory")
#define CP_WAIT1()  asm volatile("cp.async.wait_group 1;" ::: "memory")

__device__ __forceinline__ void ldsm4(uint32_t* r, uint32_t addr) {
    asm volatile("ldmatrix.sync.aligned.m8n8.x4.shared.b16 {%0,%1,%2,%3}, [%4];"
                 : "=r"(r[0]), "=r"(r[1]), "=r"(r[2]), "=r"(r[3]) : "r"(addr));
}

__device__ __forceinline__ void mma16816(float* d, const uint32_t* a,
                                         uint32_t b0, uint32_t b1) {
    asm volatile(
        "mma.sync.aligned.m16n8k16.row.col.f32.bf16.bf16.f32 "
        "{%0,%1,%2,%3}, {%4,%5,%6,%7}, {%8,%9}, {%0,%1,%2,%3};"
        : "+f"(d[0]), "+f"(d[1]), "+f"(d[2]), "+f"(d[3])
        : "r"(a[0]), "r"(a[1]), "r"(a[2]), "r"(a[3]), "r"(b0), "r"(b1));
}

__device__ __forceinline__ uint32_t pk(float x, float y) {
    __nv_bfloat162 h = __floats2bfloat162_rn(x, y);
    return *reinterpret_cast<uint32_t*>(&h);
}

// ---------------- Kernel 1: prep (optionally centers) + emb rows [row0, row0+8*nEmbBlocks) --
__global__ void __launch_bounds__(256) prep_kernel(const float* __restrict__ centers,
                                                   const float* __restrict__ emb,
                                                   float* __restrict__ out,
                                                   int n_center_blocks, int emb_row0) {
    const int bid = blockIdx.x;
    const int t = threadIdx.x;

    if (bid < n_center_blocks) {
        __shared__ float wss[8];
        const int row = bid;
        float4 v = reinterpret_cast<const float4*>(centers + (size_t)row * D_DIM)[t];
        float ss = v.x * v.x + v.y * v.y + v.z * v.z + v.w * v.w;
#pragma unroll
        for (int o = 16; o; o >>= 1) ss += __shfl_xor_sync(0xFFFFFFFFu, ss, o);
        if ((t & 31) == 0) wss[t >> 5] = ss;
        __syncthreads();
        if (t < 32) {
            float x = (t < 8) ? wss[t] : 0.f;
#pragma unroll
            for (int o = 4; o; o >>= 1) x += __shfl_xor_sync(0xFFFFFFFFu, x, o);
            if (t == 0) wss[0] = x;
        }
        __syncthreads();
        const float sc = 1.0f / fmaxf(sqrtf(wss[0]), EPS_F);

        __nv_bfloat162* orow = reinterpret_cast<__nv_bfloat162*>(g_cbf + (size_t)row * D_DIM);
        orow[t * 2]     = __floats2bfloat162_rn(v.x * sc, v.y * sc);
        orow[t * 2 + 1] = __floats2bfloat162_rn(v.z * sc, v.w * sc);

        if (row == 0 && t == 0) out[0] = 0.f;
        return;
    }

    // embeddings path
    const int lane = t & 31;
    const int wrp  = t >> 5;
    const int row  = emb_row0 + (bid - n_center_blocks) * 8 + wrp;

    const float4* src = reinterpret_cast<const float4*>(emb + (size_t)row * D_DIM);
    float4 v[8];
    float ss = 0.f;
#pragma unroll
    for (int j = 0; j < 8; ++j) {
        v[j] = src[lane + j * 32];
        ss += v[j].x * v[j].x + v[j].y * v[j].y + v[j].z * v[j].z + v[j].w * v[j].w;
    }
#pragma unroll
    for (int o = 16; o; o >>= 1) ss += __shfl_xor_sync(0xFFFFFFFFu, ss, o);
    const float sc = 1.0f / (fmaxf(sqrtf(ss), EPS_F) * TAU_F);

    uint2* dst = reinterpret_cast<uint2*>(g_ebf + (size_t)row * D_DIM);
#pragma unroll
    for (int j = 0; j < 8; ++j) {
        uint2 o;
        o.x = pk(v[j].x * sc, v[j].y * sc);
        o.y = pk(v[j].z * sc, v[j].w * sc);
        dst[lane + j * 32] = o;
    }
}

// ---------------- Kernel 2: GEMM chunk (exact R11 body), 256 thr, 2 CTAs/SM -----------
#define A_STG     16384u
#define B_STG     16384u
#define OFF_A     0u
#define OFF_B     49152u
#define OFF_MM    98304u          // 512 f
#define OFF_MS    100352u
#define OFF_MLV   102400u         // end 104448
#define SMEM_DYN  (104448 + 1024)

__global__ void __launch_bounds__(256, 2)
gemm_chunk_kernel(const long long* __restrict__ labels,
                  float* __restrict__ out, int mtile0) {
    extern __shared__ uint8_t dyn[];
    const uint32_t sb = smem_u32(dyn);
    const uint32_t base = (sb + 1023u) & ~1023u;
    uint8_t* gbase = dyn + (base - sb);

    float* sm_m  = reinterpret_cast<float*>(gbase + OFF_MM);
    float* sm_s  = reinterpret_cast<float*>(gbase + OFF_MS);
    float* sm_lv = reinterpret_cast<float*>(gbase + OFF_MLV);

    const int t     = threadIdx.x;
    const int lane  = t & 31;
    const int wid   = t >> 5;
    const int wm    = wid & 1;    // 64-row slice
    const int wn    = wid >> 1;   // 32-col slice
    const int bid   = blockIdx.x;
    const int mtile = mtile0 + (bid >> 2);
    const int chunk = bid & 3;
    const int row0  = mtile * TILE_M;

    // loader mapping: 16B chunk c = t + i*256 -> row = (t>>3) + i*32, off8 = t&7
    const int lr = t >> 3, lo = t & 7;
    uint32_t l_sw[4];
#pragma unroll
    for (int i = 0; i < 4; ++i)
        l_sw[i] = SWZ((uint32_t)((lr + i * 32) * 128 + lo * 16));
    const __nv_bfloat16* agp = g_ebf + (size_t)(row0 + lr) * D_DIM + lo * 8;
    const __nv_bfloat16* bgp = g_cbf + (size_t)(chunk * CH_N + lr) * D_DIM + lo * 8;

    // issue one quarter (A chunk i + B chunk i) of slab kb into stage stg
    auto issue_part = [&](int kb, int stg, int i) {
        const uint32_t Ad = base + OFF_A + (uint32_t)stg * A_STG;
        const uint32_t Bd = base + OFF_B + (uint32_t)stg * B_STG;
        cp16(Ad + l_sw[i], agp + kb * KSLAB + (size_t)(i * 32) * D_DIM);
        cp16(Bd + l_sw[i], bgp + kb * KSLAB + (size_t)(i * 32) * D_DIM);
    };

    float acc[4][4][4];
#pragma unroll
    for (int am = 0; am < 4; ++am)
#pragma unroll
        for (int an = 0; an < 4; ++an)
#pragma unroll
            for (int k = 0; k < 4; ++k) acc[am][an][k] = 0.f;

    // ---- prologue: stages 0,1 in flight ----
#pragma unroll
    for (int i = 0; i < 4; ++i) issue_part(0, 0, i);
    CP_COMMIT();
#pragma unroll
    for (int i = 0; i < 4; ++i) issue_part(1, 1, i);
    CP_COMMIT();

    const int rlow = lane & 15;
    const int bhi  = (lane >> 4) * 16;
    const int krot = wid & 3;     // per-warp k-step rotation (de-convoy)

#pragma unroll 1
    for (int kb = 0; kb < NSLABS; ++kb) {
        const int stg = kb % 3;
        const uint32_t Ab = base + OFF_A + (uint32_t)stg * A_STG;
        const uint32_t Bb = base + OFF_B + (uint32_t)stg * B_STG;
        const int nstg = (kb + 2) % 3;
        const bool do_issue = (kb + 2 < NSLABS);

        CP_WAIT1();              // slab kb resident (kb+1 may be pending)
        __syncthreads();         // all warps done with slab kb-1 -> stage (kb+2)%3 free

#pragma unroll
        for (int ksi = 0; ksi < 4; ++ksi) {
            const int ks = (ksi + krot) & 3;   // rotated k-step order
            // spread next-slab cp.async issue across the 4 k-steps
            if (do_issue) issue_part(kb + 2, nstg, ksi);

            const uint32_t byt = (uint32_t)(ks * 32 + bhi);
            uint32_t af[4][4], bf[2][4];
#pragma unroll
            for (int am = 0; am < 4; ++am)
                ldsm4(af[am], Ab + SWZ((uint32_t)((wm * 64 + am * 16 + rlow) * 128) + byt));
#pragma unroll
            for (int p = 0; p < 2; ++p)
                ldsm4(bf[p], Bb + SWZ((uint32_t)((wn * 32 + p * 16 + rlow) * 128) + byt));
#pragma unroll
            for (int am = 0; am < 4; ++am)
#pragma unroll
                for (int p = 0; p < 2; ++p) {
                    mma16816(acc[am][2 * p],     af[am], bf[p][0], bf[p][2]);
                    mma16816(acc[am][2 * p + 1], af[am], bf[p][1], bf[p][3]);
                }
        }
        CP_COMMIT();             // one group per slab keeps wait_group 1 aligned
    }
    __syncthreads();

    // ---- per-warp partial softmax over its 32 cols (scale pre-folded) ----
    const int ql = lane >> 2, qc = lane & 3;
#pragma unroll
    for (int am = 0; am < 4; ++am) {
#pragma unroll
        for (int h = 0; h < 2; ++h) {
            const int r = wm * 64 + am * 16 + ql + 8 * h;
            const int lc = (int)labels[row0 + r];

            float m = -1e30f;
            float v[8];
#pragma unroll
            for (int an = 0; an < 4; ++an)
#pragma unroll
                for (int e = 0; e < 2; ++e) {
                    float x = acc[am][an][2 * h + e];
                    v[an * 2 + e] = x;
                    m = fmaxf(m, x);
                }
            m = fmaxf(m, __shfl_xor_sync(0xFFFFFFFFu, m, 1));
            m = fmaxf(m, __shfl_xor_sync(0xFFFFFFFFu, m, 2));

            float s = 0.f, lv = 0.f;
#pragma unroll
            for (int an = 0; an < 4; ++an)
#pragma unroll
                for (int e = 0; e < 2; ++e) {
                    s += __expf(v[an * 2 + e] - m);
                    const int col = chunk * CH_N + wn * 32 + an * 8 + qc * 2 + e;
                    if (col == lc) lv = v[an * 2 + e];
                }
            s  += __shfl_xor_sync(0xFFFFFFFFu, s, 1);
            s  += __shfl_xor_sync(0xFFFFFFFFu, s, 2);
            lv += __shfl_xor_sync(0xFFFFFFFFu, lv, 1);
            lv += __shfl_xor_sync(0xFFFFFFFFu, lv, 2);

            if (qc == 0) {
                sm_m[wn * 128 + r]  = m;
                sm_s[wn * 128 + r]  = s;
                sm_lv[wn * 128 + r] = lv;
            }
        }
    }
    __syncthreads();

    // ---- merge 4 warp-columns, write chunk partials ----
    if (t < TILE_M) {
        float M = -1e30f;
#pragma unroll
        for (int w = 0; w < 4; ++w) M = fmaxf(M, sm_m[w * 128 + t]);
        float S = 0.f, LV = 0.f;
#pragma unroll
        for (int w = 0; w < 4; ++w) {
            S  += sm_s[w * 128 + t] * __expf(sm_m[w * 128 + t] - M);
            LV += sm_lv[w * 128 + t];
        }
        const int gr = row0 + t;
        g_pm[chunk * N_ROWS + gr]  = M;
        g_ps[chunk * N_ROWS + gr]  = S;
        g_plv[chunk * N_ROWS + gr] = LV;
        __threadfence();          // publish partials before counter bump
    }
    __syncthreads();

    // ---- fused finalize: last chunk-CTA of this mtile merges & accumulates ----
    __shared__ int s_last;
    if (t == 0) {
        int old = atomicAdd(&g_cnt[mtile], 1);
        s_last = (old == NCHUNK - 1) ? 1 : 0;
    }
    __syncthreads();
    if (s_last) {
        __threadfence();          // acquire: other chunks' partials visible
        float loss = 0.f;
        if (t < TILE_M) {
            const int gr = row0 + t;
            float M = -1e30f;
#pragma unroll
            for (int c = 0; c < NCHUNK; ++c) M = fmaxf(M, g_pm[c * N_ROWS + gr]);
            float S = 0.f, LV = 0.f;
#pragma unroll
            for (int c = 0; c < NCHUNK; ++c) {
                S  += g_ps[c * N_ROWS + gr] * __expf(g_pm[c * N_ROWS + gr] - M);
                LV += g_plv[c * N_ROWS + gr];
            }
            loss = (M + logf(S)) - LV;
        }
#pragma unroll
        for (int o = 16; o; o >>= 1) loss += __shfl_xor_sync(0xFFFFFFFFu, loss, o);
        __shared__ float wsum[8];
        if ((t & 31) == 0) wsum[t >> 5] = loss;
        __syncthreads();
        if (t < 32) {
            float x = (t < 8) ? wsum[t] : 0.f;
#pragma unroll
            for (int o = 4; o; o >>= 1) x += __shfl_xor_sync(0xFFFFFFFFu, x, o);
            if (t == 0) {
                atomicAdd(out, x * (1.0f / (float)N_ROWS));
                g_cnt[mtile] = 0;   // self-reset for next graph replay
            }
        }
    }
}

// ---------------- Launch: stream-forked overlap of prep(half1) with gemm(half0) -------
#define HALF_ROWS   (N_ROWS / 2)
#define EMB_BLKS    (HALF_ROWS / 8)      // 4096 blocks per half
#define GEMM_BLKS   ((HALF_ROWS / TILE_M) * NCHUNK)   // 1024 per half

extern "C" void kernel_launch(void* const* d_in, const int* in_sizes, int n_in,
                              void* d_out, int out_size) {
    const float* emb       = (const float*)d_in[0];
    const float* centers   = (const float*)d_in[1];
    const long long* label = (const long long*)d_in[2];
    float* out             = (float*)d_out;

    // One-time host-side resources (no device memory allocated).
    static cudaStream_t s2 = nullptr;
    static cudaEvent_t  e1 = nullptr, e3 = nullptr;
    if (s2 == nullptr) {
        cudaStreamCreateWithFlags(&s2, cudaStreamNonBlocking);
        cudaEventCreateWithFlags(&e1, cudaEventDisableTiming);
        cudaEventCreateWithFlags(&e3, cudaEventDisableTiming);
    }

    cudaFuncSetAttribute(gemm_chunk_kernel, cudaFuncAttributeMaxDynamicSharedMemorySize, SMEM_DYN);

    // k0: centers + emb half0 (origin stream)
    prep_kernel<<<512 + EMB_BLKS, 256>>>(centers, emb, out, 512, 0);
    cudaEventRecord(e1, 0);

    // s2 branch: emb half1, then gemm half1 (depends on k0 via e1 for centers)
    cudaStreamWaitEvent(s2, e1, 0);
    prep_kernel<<<EMB_BLKS, 256, 0, s2>>>(centers, emb, out, 0, HALF_ROWS);
    gemm_chunk_kernel<<<GEMM_BLKS, 256, SMEM_DYN, s2>>>(label, out, HALF_ROWS / TILE_M);
    cudaEventRecord(e3, s2);

    // origin branch: gemm half0 (concurrent with s2 branch)
    gemm_chunk_kernel<<<GEMM_BLKS, 256, SMEM_DYN>>>(label, out, 0);

    // join
    cudaStreamWaitEvent(0, e3, 0);
}

// round 15
// speedup vs baseline: 1.1042x; 1.0527x over previous
#include <cuda_runtime.h>
#include <cuda_fp16.h>
#include <cstdint>

#define N_ROWS   65536
#define K_CENT   512
#define D_DIM    1024
#define TILE_M   128
#define CH_N     256          // centers per chunk
#define NCHUNK   2
#define KSLAB    32
#define NSLABS   (D_DIM / KSLAB)   // 32
#define TAU_F    0.1f
#define EPS_F    1e-8f

// Normalized centers in fp16 (1/||c|| folded), row-major [K_CENT][D_DIM]
__device__ __align__(16) __half g_cbf[K_CENT * D_DIM];
// Normalized embeddings in fp16 with 1/(||e||*tau) folded, [N_ROWS][D_DIM]
__device__ __align__(16) __half g_ebf[(size_t)N_ROWS * D_DIM];
// Per-chunk partial softmax stats
__device__ float g_pm[NCHUNK * N_ROWS];
__device__ float g_ps[NCHUNK * N_ROWS];
__device__ float g_plv[NCHUNK * N_ROWS];
// Per-mtile completion counters (self-resetting each replay)
__device__ int g_cnt[N_ROWS / TILE_M];

// ---------------- helpers ----------------
__device__ __forceinline__ uint32_t smem_u32(const void* p) {
    uint32_t a;
    asm("{ .reg .u64 t; cvta.to.shared.u64 t, %1; cvt.u32.u64 %0, t; }" : "=r"(a) : "l"(p));
    return a;
}
// SW64 swizzle for 64B rows
#define SWZ64(o) ((o) ^ ((((uint32_t)(o)) >> 3) & 0x30u))

__device__ __forceinline__ void cp16(uint32_t dst, const void* src) {
    asm volatile("cp.async.cg.shared.global [%0], [%1], 16;"
                 :: "r"(dst), "l"(__cvta_generic_to_global(src)) : "memory");
}
#define CP_COMMIT() asm volatile("cp.async.commit_group;" ::: "memory")
#define CP_WAIT2()  asm volatile("cp.async.wait_group 2;" ::: "memory")

__device__ __forceinline__ void ldsm4(uint32_t* r, uint32_t addr) {
    asm volatile("ldmatrix.sync.aligned.m8n8.x4.shared.b16 {%0,%1,%2,%3}, [%4];"
                 : "=r"(r[0]), "=r"(r[1]), "=r"(r[2]), "=r"(r[3]) : "r"(addr));
}

// fp16-accumulate HMMA: D(2 regs f16x2) = A(4) * B(2) + D
__device__ __forceinline__ void mma_h(uint32_t* d, const uint32_t* a,
                                      uint32_t b0, uint32_t b1) {
    asm volatile(
        "mma.sync.aligned.m16n8k16.row.col.f16.f16.f16.f16 "
        "{%0,%1}, {%2,%3,%4,%5}, {%6,%7}, {%0,%1};"
        : "+r"(d[0]), "+r"(d[1])
        : "r"(a[0]), "r"(a[1]), "r"(a[2]), "r"(a[3]), "r"(b0), "r"(b1));
}

// ---------------- Kernel 1: merged prep (centers + embeddings) -> fp16 ----------------
#define PREP_CENTER_BLOCKS 512
__global__ void __launch_bounds__(256) prep_kernel(const float* __restrict__ centers,
                                                   const float* __restrict__ emb,
                                                   float* __restrict__ out) {
    const int bid = blockIdx.x;
    const int t = threadIdx.x;

    if (bid < PREP_CENTER_BLOCKS) {
        __shared__ float wss[8];
        const int row = bid;
        float4 v = reinterpret_cast<const float4*>(centers + (size_t)row * D_DIM)[t];
        float ss = v.x * v.x + v.y * v.y + v.z * v.z + v.w * v.w;
#pragma unroll
        for (int o = 16; o; o >>= 1) ss += __shfl_xor_sync(0xFFFFFFFFu, ss, o);
        if ((t & 31) == 0) wss[t >> 5] = ss;
        __syncthreads();
        if (t < 32) {
            float x = (t < 8) ? wss[t] : 0.f;
#pragma unroll
            for (int o = 4; o; o >>= 1) x += __shfl_xor_sync(0xFFFFFFFFu, x, o);
            if (t == 0) wss[0] = x;
        }
        __syncthreads();
        const float sc = 1.0f / fmaxf(sqrtf(wss[0]), EPS_F);

        __half2* orow = reinterpret_cast<__half2*>(g_cbf + (size_t)row * D_DIM);
        orow[t * 2]     = __floats2half2_rn(v.x * sc, v.y * sc);
        orow[t * 2 + 1] = __floats2half2_rn(v.z * sc, v.w * sc);

        if (row == 0 && t == 0) out[0] = 0.f;
        return;
    }

    // embeddings path
    const int lane = t & 31;
    const int wrp  = t >> 5;
    const int row  = (bid - PREP_CENTER_BLOCKS) * 8 + wrp;

    const float4* src = reinterpret_cast<const float4*>(emb + (size_t)row * D_DIM);
    float4 v[8];
    float ss = 0.f;
#pragma unroll
    for (int j = 0; j < 8; ++j) {
        v[j] = src[lane + j * 32];
        ss += v[j].x * v[j].x + v[j].y * v[j].y + v[j].z * v[j].z + v[j].w * v[j].w;
    }
#pragma unroll
    for (int o = 16; o; o >>= 1) ss += __shfl_xor_sync(0xFFFFFFFFu, ss, o);
    const float sc = 1.0f / (fmaxf(sqrtf(ss), EPS_F) * TAU_F);

    __half2* dst = reinterpret_cast<__half2*>(g_ebf + (size_t)row * D_DIM);
#pragma unroll
    for (int j = 0; j < 8; ++j) {
        dst[(lane + j * 32) * 2]     = __floats2half2_rn(v[j].x * sc, v[j].y * sc);
        dst[(lane + j * 32) * 2 + 1] = __floats2half2_rn(v[j].z * sc, v[j].w * sc);
    }
}

// ---------------- Kernel 2: fp16-acc GEMM, warp tile 64x64, 2 CTAs/SM ----------------
// grid = 1024: mtile = bid>>1 (128 rows), chunk = bid&1 (256 centers)
// 8 warps 2(m)x4(n): warp tile 64 rows x 64 cols, acc 64 f16x2 regs
// SMEM: A 4x8192 @0 (=32768); B 4x16384 @32768 (=65536) -> 98304; stats after.
#define A_STG     8192u
#define B_STG     16384u
#define OFF_A     0u
#define OFF_B     32768u
#define OFF_MM    98304u          // 512 f
#define OFF_MS    100352u
#define OFF_MLV   102400u         // end 104448
#define SMEM_DYN  (104448 + 1024)

__global__ void __launch_bounds__(256, 2)
gemm_chunk_kernel(const long long* __restrict__ labels,
                  float* __restrict__ out) {
    extern __shared__ uint8_t dyn[];
    const uint32_t sb = smem_u32(dyn);
    const uint32_t base = (sb + 1023u) & ~1023u;
    uint8_t* gbase = dyn + (base - sb);

    float* sm_m  = reinterpret_cast<float*>(gbase + OFF_MM);
    float* sm_s  = reinterpret_cast<float*>(gbase + OFF_MS);
    float* sm_lv = reinterpret_cast<float*>(gbase + OFF_MLV);

    const int t     = threadIdx.x;
    const int lane  = t & 31;
    const int wid   = t >> 5;
    const int wm    = wid & 1;    // 64-row slice
    const int wn    = wid >> 1;   // 64-col slice
    const int bid   = blockIdx.x;
    const int mtile = bid >> 1;
    const int chunk = bid & 1;
    const int row0  = mtile * TILE_M;

    // loader mapping: 16B chunk c -> row = c>>2, ch = c&3 (64B rows)
    const int lr = t >> 2, lch = t & 3;
    uint32_t swA[2], swB[4];
#pragma unroll
    for (int i = 0; i < 2; ++i)
        swA[i] = SWZ64((uint32_t)((lr + i * 64) * 64 + lch * 16));
#pragma unroll
    for (int i = 0; i < 4; ++i)
        swB[i] = SWZ64((uint32_t)((lr + i * 64) * 64 + lch * 16));
    const __half* agp = g_ebf + (size_t)(row0 + lr) * D_DIM + lch * 8;
    const __half* bgp = g_cbf + (size_t)(chunk * CH_N + lr) * D_DIM + lch * 8;

    // issue half a slab: part 0 = A(both) + B0; part 1 = B1..B3
    auto issue_part = [&](int kb, int stg, int part) {
        const uint32_t Ad = base + OFF_A + (uint32_t)stg * A_STG;
        const uint32_t Bd = base + OFF_B + (uint32_t)stg * B_STG;
        if (part == 0) {
            cp16(Ad + swA[0], agp + kb * KSLAB);
            cp16(Ad + swA[1], agp + kb * KSLAB + (size_t)64 * D_DIM);
            cp16(Bd + swB[0], bgp + kb * KSLAB);
        } else {
#pragma unroll
            for (int i = 1; i < 4; ++i)
                cp16(Bd + swB[i], bgp + kb * KSLAB + (size_t)(i * 64) * D_DIM);
        }
    };

    uint32_t acc[4][8][2];
#pragma unroll
    for (int am = 0; am < 4; ++am)
#pragma unroll
        for (int nt = 0; nt < 8; ++nt) { acc[am][nt][0] = 0u; acc[am][nt][1] = 0u; }

    // ---- prologue: stages 0..2 in flight ----
#pragma unroll
    for (int s = 0; s < 3; ++s) {
        issue_part(s, s, 0); issue_part(s, s, 1); CP_COMMIT();
    }

    const int rlow = lane & 15;
    const int bhi  = (lane >> 4) * 16;
    const int krot = wid & 1;     // per-warp k-step rotation (2 steps/slab)

#pragma unroll 1
    for (int kb = 0; kb < NSLABS; ++kb) {
        const int stg = kb & 3;
        const uint32_t Ab = base + OFF_A + (uint32_t)stg * A_STG;
        const uint32_t Bb = base + OFF_B + (uint32_t)stg * B_STG;
        const int nstg = (kb + 3) & 3;
        const bool do_issue = (kb + 3 < NSLABS);

        CP_WAIT2();              // slab kb resident (2 newer groups pending)
        __syncthreads();         // all warps past slab kb-1 -> stage reuse safe

#pragma unroll
        for (int ksi = 0; ksi < 2; ++ksi) {
            const int ks = (ksi + krot) & 1;   // rotated k-step order
            if (do_issue) issue_part(kb + 3, nstg, ksi);  // spread DMA issue

            const uint32_t byt = (uint32_t)(ks * 32 + bhi);
            uint32_t af[4][4], bf[4][4];
#pragma unroll
            for (int am = 0; am < 4; ++am)
                ldsm4(af[am], Ab + SWZ64((uint32_t)((wm * 64 + am * 16 + rlow) * 64) + byt));
#pragma unroll
            for (int p = 0; p < 4; ++p)
                ldsm4(bf[p], Bb + SWZ64((uint32_t)((wn * 64 + p * 16 + rlow) * 64) + byt));
#pragma unroll
            for (int am = 0; am < 4; ++am)
#pragma unroll
                for (int p = 0; p < 4; ++p) {
                    mma_h(acc[am][2 * p],     af[am], bf[p][0], bf[p][2]);
                    mma_h(acc[am][2 * p + 1], af[am], bf[p][1], bf[p][3]);
                }
        }
        CP_COMMIT();             // one group per slab keeps wait_group 2 aligned
    }
    __syncthreads();

    // ---- per-warp partial softmax over its 64 cols (scale pre-folded) ----
    const int ql = lane >> 2, qc = lane & 3;
#pragma unroll
    for (int am = 0; am < 4; ++am) {
#pragma unroll
        for (int h = 0; h < 2; ++h) {
            const int r = wm * 64 + am * 16 + ql + 8 * h;
            const int lc = (int)labels[row0 + r];

            float m = -1e30f;
            float v[16];
#pragma unroll
            for (int nt = 0; nt < 8; ++nt) {
                const __half2 hv = *reinterpret_cast<const __half2*>(&acc[am][nt][h]);
                const float2 f2 = __half22float2(hv);
                v[nt * 2]     = f2.x;
                v[nt * 2 + 1] = f2.y;
                m = fmaxf(m, fmaxf(f2.x, f2.y));
            }
            m = fmaxf(m, __shfl_xor_sync(0xFFFFFFFFu, m, 1));
            m = fmaxf(m, __shfl_xor_sync(0xFFFFFFFFu, m, 2));

            float s = 0.f, lv = 0.f;
#pragma unroll
            for (int nt = 0; nt < 8; ++nt)
#pragma unroll
                for (int e = 0; e < 2; ++e) {
                    s += __expf(v[nt * 2 + e] - m);
                    const int col = chunk * CH_N + wn * 64 + nt * 8 + qc * 2 + e;
                    if (col == lc) lv = v[nt * 2 + e];
                }
            s  += __shfl_xor_sync(0xFFFFFFFFu, s, 1);
            s  += __shfl_xor_sync(0xFFFFFFFFu, s, 2);
            lv += __shfl_xor_sync(0xFFFFFFFFu, lv, 1);
            lv += __shfl_xor_sync(0xFFFFFFFFu, lv, 2);

            if (qc == 0) {
                sm_m[wn * 128 + r]  = m;
                sm_s[wn * 128 + r]  = s;
                sm_lv[wn * 128 + r] = lv;
            }
        }
    }
    __syncthreads();

    // ---- merge 4 warp-columns, write chunk partials ----
    if (t < TILE_M) {
        float M = -1e30f;
#pragma unroll
        for (int w = 0; w < 4; ++w) M = fmaxf(M, sm_m[w * 128 + t]);
        float S = 0.f, LV = 0.f;
#pragma unroll
        for (int w = 0; w < 4; ++w) {
            S  += sm_s[w * 128 + t] * __expf(sm_m[w * 128 + t] - M);
            LV += sm_lv[w * 128 + t];
        }
        const int gr = row0 + t;
        g_pm[chunk * N_ROWS + gr]  = M;
        g_ps[chunk * N_ROWS + gr]  = S;
        g_plv[chunk * N_ROWS + gr] = LV;
        __threadfence();          // publish partials before counter bump
    }
    __syncthreads();

    // ---- fused finalize: last chunk-CTA of this mtile merges & accumulates ----
    __shared__ int s_last;
    if (t == 0) {
        int old = atomicAdd(&g_cnt[mtile], 1);
        s_last = (old == NCHUNK - 1) ? 1 : 0;
    }
    __syncthreads();
    if (s_last) {
        __threadfence();          // acquire: other chunk's partials visible
        float loss = 0.f;
        if (t < TILE_M) {
            const int gr = row0 + t;
            float M = -1e30f;
#pragma unroll
            for (int c = 0; c < NCHUNK; ++c) M = fmaxf(M, g_pm[c * N_ROWS + gr]);
            float S = 0.f, LV = 0.f;
#pragma unroll
            for (int c = 0; c < NCHUNK; ++c) {
                S  += g_ps[c * N_ROWS + gr] * __expf(g_pm[c * N_ROWS + gr] - M);
                LV += g_plv[c * N_ROWS + gr];
            }
            loss = (M + logf(S)) - LV;
        }
#pragma unroll
        for (int o = 16; o; o >>= 1) loss += __shfl_xor_sync(0xFFFFFFFFu, loss, o);
        __shared__ float wsum[8];
        if ((t & 31) == 0) wsum[t >> 5] = loss;
        __syncthreads();
        if (t < 32) {
            float x = (t < 8) ? wsum[t] : 0.f;
#pragma unroll
            for (int o = 4; o; o >>= 1) x += __shfl_xor_sync(0xFFFFFFFFu, x, o);
            if (t == 0) {
                atomicAdd(out, x * (1.0f / (float)N_ROWS));
                g_cnt[mtile] = 0;   // self-reset for next graph replay
            }
        }
    }
}

// ---------------- Launch (serial; stream fork proven useless at full RF) -------------
extern "C" void kernel_launch(void* const* d_in, const int* in_sizes, int n_in,
                              void* d_out, int out_size) {
    const float* emb       = (const float*)d_in[0];
    const float* centers   = (const float*)d_in[1];
    const long long* label = (const long long*)d_in[2];
    float* out             = (float*)d_out;

    cudaFuncSetAttribute(gemm_chunk_kernel, cudaFuncAttributeMaxDynamicSharedMemorySize, SMEM_DYN);

    prep_kernel<<<PREP_CENTER_BLOCKS + N_ROWS / 8, 256>>>(centers, emb, out);
    gemm_chunk_kernel<<<(N_ROWS / TILE_M) * NCHUNK, 256, SMEM_DYN>>>(label, out);
}

// round 16
// speedup vs baseline: 1.1187x; 1.0131x over previous
#include <cuda_runtime.h>
#include <cuda_fp16.h>
#include <cstdint>

#define N_ROWS   65536
#define K_CENT   512
#define D_DIM    1024
#define TILE_M   128
#define CH_N     256          // centers per chunk
#define NCHUNK   2
#define KSLAB    32
#define NSLABS   (D_DIM / KSLAB)   // 32
#define TAU_F    0.1f
#define EPS_F    1e-8f

// Normalized centers in fp16 (1/||c|| folded), row-major [K_CENT][D_DIM]
__device__ __align__(16) __half g_cbf[K_CENT * D_DIM];
// Normalized embeddings in fp16 with 1/(||e||*tau) folded, [N_ROWS][D_DIM]
__device__ __align__(16) __half g_ebf[(size_t)N_ROWS * D_DIM];
// Per-chunk partial softmax stats
__device__ float g_pm[NCHUNK * N_ROWS];
__device__ float g_ps[NCHUNK * N_ROWS];
__device__ float g_plv[NCHUNK * N_ROWS];
// Per-mtile completion counters (self-resetting each replay)
__device__ int g_cnt[N_ROWS / TILE_M];

// ---------------- helpers ----------------
__device__ __forceinline__ uint32_t smem_u32(const void* p) {
    uint32_t a;
    asm("{ .reg .u64 t; cvta.to.shared.u64 t, %1; cvt.u32.u64 %0, t; }" : "=r"(a) : "l"(p));
    return a;
}
// SW64 swizzle for 64B rows
#define SWZ64(o) ((o) ^ ((((uint32_t)(o)) >> 3) & 0x30u))

__device__ __forceinline__ void cp16(uint32_t dst, const void* src) {
    asm volatile("cp.async.cg.shared.global [%0], [%1], 16;"
                 :: "r"(dst), "l"(__cvta_generic_to_global(src)) : "memory");
}
#define CP_COMMIT() asm volatile("cp.async.commit_group;" ::: "memory")
#define CP_WAIT2()  asm volatile("cp.async.wait_group 2;" ::: "memory")

__device__ __forceinline__ void ldsm4(uint32_t* r, uint32_t addr) {
    asm volatile("ldmatrix.sync.aligned.m8n8.x4.shared.b16 {%0,%1,%2,%3}, [%4];"
                 : "=r"(r[0]), "=r"(r[1]), "=r"(r[2]), "=r"(r[3]) : "r"(addr));
}

// fp16-accumulate HMMA: D(2 regs f16x2) = A(4) * B(2) + D
__device__ __forceinline__ void mma_h(uint32_t* d, const uint32_t* a,
                                      uint32_t b0, uint32_t b1) {
    asm volatile(
        "mma.sync.aligned.m16n8k16.row.col.f16.f16.f16.f16 "
        "{%0,%1}, {%2,%3,%4,%5}, {%6,%7}, {%0,%1};"
        : "+r"(d[0]), "+r"(d[1])
        : "r"(a[0]), "r"(a[1]), "r"(a[2]), "r"(a[3]), "r"(b0), "r"(b1));
}

// ---------------- Kernel 1: merged prep (centers + embeddings) -> fp16 ----------------
#define PREP_CENTER_BLOCKS 512
__global__ void __launch_bounds__(256) prep_kernel(const float* __restrict__ centers,
                                                   const float* __restrict__ emb,
                                                   float* __restrict__ out) {
    const int bid = blockIdx.x;
    const int t = threadIdx.x;

    if (bid < PREP_CENTER_BLOCKS) {
        __shared__ float wss[8];
        const int row = bid;
        float4 v = reinterpret_cast<const float4*>(centers + (size_t)row * D_DIM)[t];
        float ss = v.x * v.x + v.y * v.y + v.z * v.z + v.w * v.w;
#pragma unroll
        for (int o = 16; o; o >>= 1) ss += __shfl_xor_sync(0xFFFFFFFFu, ss, o);
        if ((t & 31) == 0) wss[t >> 5] = ss;
        __syncthreads();
        if (t < 32) {
            float x = (t < 8) ? wss[t] : 0.f;
#pragma unroll
            for (int o = 4; o; o >>= 1) x += __shfl_xor_sync(0xFFFFFFFFu, x, o);
            if (t == 0) wss[0] = x;
        }
        __syncthreads();
        const float sc = 1.0f / fmaxf(sqrtf(wss[0]), EPS_F);

        __half2* orow = reinterpret_cast<__half2*>(g_cbf + (size_t)row * D_DIM);
        orow[t * 2]     = __floats2half2_rn(v.x * sc, v.y * sc);
        orow[t * 2 + 1] = __floats2half2_rn(v.z * sc, v.w * sc);

        if (row == 0 && t == 0) out[0] = 0.f;
        return;
    }

    // embeddings path
    const int lane = t & 31;
    const int wrp  = t >> 5;
    const int row  = (bid - PREP_CENTER_BLOCKS) * 8 + wrp;

    const float4* src = reinterpret_cast<const float4*>(emb + (size_t)row * D_DIM);
    float4 v[8];
    float ss = 0.f;
#pragma unroll
    for (int j = 0; j < 8; ++j) {
        v[j] = src[lane + j * 32];
        ss += v[j].x * v[j].x + v[j].y * v[j].y + v[j].z * v[j].z + v[j].w * v[j].w;
    }
#pragma unroll
    for (int o = 16; o; o >>= 1) ss += __shfl_xor_sync(0xFFFFFFFFu, ss, o);
    const float sc = 1.0f / (fmaxf(sqrtf(ss), EPS_F) * TAU_F);

    __half2* dst = reinterpret_cast<__half2*>(g_ebf + (size_t)row * D_DIM);
#pragma unroll
    for (int j = 0; j < 8; ++j) {
        dst[(lane + j * 32) * 2]     = __floats2half2_rn(v[j].x * sc, v[j].y * sc);
        dst[(lane + j * 32) * 2 + 1] = __floats2half2_rn(v[j].z * sc, v[j].w * sc);
    }
}

// ---------------- Kernel 2: fp16-acc GEMM, warp tile 64x64, 2 CTAs/SM ----------------
// grid = 1024: mtile = bid>>1 (128 rows), chunk = bid&1 (256 centers)
// 8 warps 2(m)x4(n): warp tile 64 rows x 64 cols, acc 64 f16x2 regs
// SMEM: A 4x8192 @0 (=32768); B 4x16384 @32768 (=65536) -> 98304; stats after.
#define A_STG     8192u
#define B_STG     16384u
#define OFF_A     0u
#define OFF_B     32768u
#define OFF_MM    98304u          // 512 f
#define OFF_MS    100352u
#define OFF_MLV   102400u         // end 104448
#define SMEM_DYN  (104448 + 1024)

__global__ void __launch_bounds__(256, 2)
gemm_chunk_kernel(const long long* __restrict__ labels,
                  float* __restrict__ out) {
    extern __shared__ uint8_t dyn[];
    const uint32_t sb = smem_u32(dyn);
    const uint32_t base = (sb + 1023u) & ~1023u;
    uint8_t* gbase = dyn + (base - sb);

    float* sm_m  = reinterpret_cast<float*>(gbase + OFF_MM);
    float* sm_s  = reinterpret_cast<float*>(gbase + OFF_MS);
    float* sm_lv = reinterpret_cast<float*>(gbase + OFF_MLV);

    const int t     = threadIdx.x;
    const int lane  = t & 31;
    const int wid   = t >> 5;
    const int wm    = wid & 1;    // 64-row slice
    const int wn    = wid >> 1;   // 64-col slice
    const int bid   = blockIdx.x;
    const int mtile = bid >> 1;
    const int chunk = bid & 1;
    const int row0  = mtile * TILE_M;

    // loader mapping: 16B chunk c -> row = c>>2, ch = c&3 (64B rows)
    const int lr = t >> 2, lch = t & 3;
    uint32_t swA[2], swB[4];
#pragma unroll
    for (int i = 0; i < 2; ++i)
        swA[i] = SWZ64((uint32_t)((lr + i * 64) * 64 + lch * 16));
#pragma unroll
    for (int i = 0; i < 4; ++i)
        swB[i] = SWZ64((uint32_t)((lr + i * 64) * 64 + lch * 16));
    const __half* agp = g_ebf + (size_t)(row0 + lr) * D_DIM + lch * 8;
    const __half* bgp = g_cbf + (size_t)(chunk * CH_N + lr) * D_DIM + lch * 8;

    // issue half a slab: part 0 = A(both) + B0; part 1 = B1..B3
    auto issue_part = [&](int kb, int stg, int part) {
        const uint32_t Ad = base + OFF_A + (uint32_t)stg * A_STG;
        const uint32_t Bd = base + OFF_B + (uint32_t)stg * B_STG;
        if (part == 0) {
            cp16(Ad + swA[0], agp + kb * KSLAB);
            cp16(Ad + swA[1], agp + kb * KSLAB + (size_t)64 * D_DIM);
            cp16(Bd + swB[0], bgp + kb * KSLAB);
        } else {
#pragma unroll
            for (int i = 1; i < 4; ++i)
                cp16(Bd + swB[i], bgp + kb * KSLAB + (size_t)(i * 64) * D_DIM);
        }
    };

    uint32_t acc[4][8][2];
#pragma unroll
    for (int am = 0; am < 4; ++am)
#pragma unroll
        for (int nt = 0; nt < 8; ++nt) { acc[am][nt][0] = 0u; acc[am][nt][1] = 0u; }

    // ---- prologue: stages 0..2 in flight ----
#pragma unroll
    for (int s = 0; s < 3; ++s) {
        issue_part(s, s, 0); issue_part(s, s, 1); CP_COMMIT();
    }

    const int rlow = lane & 15;
    const int bhi  = (lane >> 4) * 16;
    const int krot = wid & 1;     // per-warp k-step rotation (2 steps/slab)

    // Precomputed, loop-invariant swizzled ldsm offsets (ks=0 basis).
    // SW64's XOR mask depends only on row bits; the k-step bit (<<5) is
    // disjoint, so the per-step address is aoff ^ (ks<<5).
    uint32_t aoff[4], boff[4];
#pragma unroll
    for (int am = 0; am < 4; ++am)
        aoff[am] = SWZ64((uint32_t)((wm * 64 + am * 16 + rlow) * 64 + bhi));
#pragma unroll
    for (int p = 0; p < 4; ++p)
        boff[p] = SWZ64((uint32_t)((wn * 64 + p * 16 + rlow) * 64 + bhi));

#pragma unroll 1
    for (int kb = 0; kb < NSLABS; ++kb) {
        const int stg = kb & 3;
        const uint32_t Ab = base + OFF_A + (uint32_t)stg * A_STG;
        const uint32_t Bb = base + OFF_B + (uint32_t)stg * B_STG;
        const int nstg = (kb + 3) & 3;
        const bool do_issue = (kb + 3 < NSLABS);

        CP_WAIT2();              // slab kb resident (2 newer groups pending)
        __syncthreads();         // all warps past slab kb-1 -> stage reuse safe

#pragma unroll
        for (int ksi = 0; ksi < 2; ++ksi) {
            const int ks = (ksi + krot) & 1;   // rotated k-step order
            if (do_issue) issue_part(kb + 3, nstg, ksi);  // spread DMA issue

            const uint32_t kx = (uint32_t)(ks << 5);
            uint32_t af[4][4], bf[4][4];
#pragma unroll
            for (int am = 0; am < 4; ++am)
                ldsm4(af[am], Ab + (aoff[am] ^ kx));
#pragma unroll
            for (int p = 0; p < 4; ++p)
                ldsm4(bf[p], Bb + (boff[p] ^ kx));
#pragma unroll
            for (int am = 0; am < 4; ++am)
#pragma unroll
                for (int p = 0; p < 4; ++p) {
                    mma_h(acc[am][2 * p],     af[am], bf[p][0], bf[p][2]);
                    mma_h(acc[am][2 * p + 1], af[am], bf[p][1], bf[p][3]);
                }
        }
        CP_COMMIT();             // one group per slab keeps wait_group 2 aligned
    }
    __syncthreads();

    // ---- per-warp partial softmax over its 64 cols (scale pre-folded) ----
    const int ql = lane >> 2, qc = lane & 3;
#pragma unroll
    for (int am = 0; am < 4; ++am) {
#pragma unroll
        for (int h = 0; h < 2; ++h) {
            const int r = wm * 64 + am * 16 + ql + 8 * h;
            const int lc = (int)labels[row0 + r];

            float m = -1e30f;
            float v[16];
#pragma unroll
            for (int nt = 0; nt < 8; ++nt) {
                const __half2 hv = *reinterpret_cast<const __half2*>(&acc[am][nt][h]);
                const float2 f2 = __half22float2(hv);
                v[nt * 2]     = f2.x;
                v[nt * 2 + 1] = f2.y;
                m = fmaxf(m, fmaxf(f2.x, f2.y));
            }
            m = fmaxf(m, __shfl_xor_sync(0xFFFFFFFFu, m, 1));
            m = fmaxf(m, __shfl_xor_sync(0xFFFFFFFFu, m, 2));

            float s = 0.f, lv = 0.f;
#pragma unroll
            for (int nt = 0; nt < 8; ++nt)
#pragma unroll
                for (int e = 0; e < 2; ++e) {
                    s += __expf(v[nt * 2 + e] - m);
                    const int col = chunk * CH_N + wn * 64 + nt * 8 + qc * 2 + e;
                    if (col == lc) lv = v[nt * 2 + e];
                }
            s  += __shfl_xor_sync(0xFFFFFFFFu, s, 1);
            s  += __shfl_xor_sync(0xFFFFFFFFu, s, 2);
            lv += __shfl_xor_sync(0xFFFFFFFFu, lv, 1);
            lv += __shfl_xor_sync(0xFFFFFFFFu, lv, 2);

            if (qc == 0) {
                sm_m[wn * 128 + r]  = m;
                sm_s[wn * 128 + r]  = s;
                sm_lv[wn * 128 + r] = lv;
            }
        }
    }
    __syncthreads();

    // ---- merge 4 warp-columns, write chunk partials ----
    if (t < TILE_M) {
        float M = -1e30f;
#pragma unroll
        for (int w = 0; w < 4; ++w) M = fmaxf(M, sm_m[w * 128 + t]);
        float S = 0.f, LV = 0.f;
#pragma unroll
        for (int w = 0; w < 4; ++w) {
            S  += sm_s[w * 128 + t] * __expf(sm_m[w * 128 + t] - M);
            LV += sm_lv[w * 128 + t];
        }
        const int gr = row0 + t;
        g_pm[chunk * N_ROWS + gr]  = M;
        g_ps[chunk * N_ROWS + gr]  = S;
        g_plv[chunk * N_ROWS + gr] = LV;
        __threadfence();          // publish partials before counter bump
    }
    __syncthreads();

    // ---- fused finalize: last chunk-CTA of this mtile merges & accumulates ----
    __shared__ int s_last;
    if (t == 0) {
        int old = atomicAdd(&g_cnt[mtile], 1);
        s_last = (old == NCHUNK - 1) ? 1 : 0;
    }
    __syncthreads();
    if (s_last) {
        __threadfence();          // acquire: other chunk's partials visible
        float loss = 0.f;
        if (t < TILE_M) {
            const int gr = row0 + t;
            float M = -1e30f;
#pragma unroll
            for (int c = 0; c < NCHUNK; ++c) M = fmaxf(M, g_pm[c * N_ROWS + gr]);
            float S = 0.f, LV = 0.f;
#pragma unroll
            for (int c = 0; c < NCHUNK; ++c) {
                S  += g_ps[c * N_ROWS + gr] * __expf(g_pm[c * N_ROWS + gr] - M);
                LV += g_plv[c * N_ROWS + gr];
            }
            loss = (M + logf(S)) - LV;
        }
#pragma unroll
        for (int o = 16; o; o >>= 1) loss += __shfl_xor_sync(0xFFFFFFFFu, loss, o);
        __shared__ float wsum[8];
        if ((t & 31) == 0) wsum[t >> 5] = loss;
        __syncthreads();
        if (t < 32) {
            float x = (t < 8) ? wsum[t] : 0.f;
#pragma unroll
            for (int o = 4; o; o >>= 1) x += __shfl_xor_sync(0xFFFFFFFFu, x, o);
            if (t == 0) {
                atomicAdd(out, x * (1.0f / (float)N_ROWS));
                g_cnt[mtile] = 0;   // self-reset for next graph replay
            }
        }
    }
}

// ---------------- Launch ----------------
extern "C" void kernel_launch(void* const* d_in, const int* in_sizes, int n_in,
                              void* d_out, int out_size) {
    const float* emb       = (const float*)d_in[0];
    const float* centers   = (const float*)d_in[1];
    const long long* label = (const long long*)d_in[2];
    float* out             = (float*)d_out;

    cudaFuncSetAttribute(gemm_chunk_kernel, cudaFuncAttributeMaxDynamicSharedMemorySize, SMEM_DYN);

    prep_kernel<<<PREP_CENTER_BLOCKS + N_ROWS / 8, 256>>>(centers, emb, out);
    gemm_chunk_kernel<<<(N_ROWS / TILE_M) * NCHUNK, 256, SMEM_DYN>>>(label, out);
}